// round 1
// baseline (speedup 1.0000x reference)
#include <cuda_runtime.h>
#include <cuda_bf16.h>
#include <math.h>

#define T_TOK   8192
#define D_DIM   1024
#define E_EXP   8
#define H_DIM   4096
#define BM      128
#define MAX_TILES (2 * T_TOK / BM + E_EXP)     // 136
#define MAX_SLOTS (MAX_TILES * BM)             // 17408

// ---------------- scratch (static device globals: allocation-guard safe) ---
__device__ int   g_counts[E_EXP];
__device__ int   g_cursor[E_EXP];
__device__ int   g_offp[E_EXP + 1];
__device__ int   g_tile_expert[MAX_TILES];
__device__ int   g_tok[MAX_SLOTS];
__device__ int   g_slotof[T_TOK * 2];
__device__ int   g_topi[T_TOK * 2];
__device__ float g_topw[T_TOK * 2];
__device__ float g_h[(size_t)MAX_SLOTS * H_DIM];   // GEMM1 output (gelu'd)
__device__ float g_y[(size_t)MAX_SLOTS * D_DIM];   // GEMM2 output (incl. b2)

// ---------------- init: zero counters, mark all slots dummy ----------------
__global__ void init_kernel() {
    int i = blockIdx.x * blockDim.x + threadIdx.x;
    if (i < E_EXP) { g_counts[i] = 0; g_cursor[i] = 0; }
    if (i < MAX_SLOTS) g_tok[i] = -1;
}

// ---------------- router: one warp per token -------------------------------
__global__ void router_kernel(const float* __restrict__ x,
                              const float* __restrict__ Wg,
                              const float* __restrict__ bg) {
    int t    = (blockIdx.x * blockDim.x + threadIdx.x) >> 5;
    int lane = threadIdx.x & 31;
    if (t >= T_TOK) return;
    const float* xr = x + (size_t)t * D_DIM;

    float acc[E_EXP];
#pragma unroll
    for (int e = 0; e < E_EXP; e++) acc[e] = 0.f;

    for (int d = lane; d < D_DIM; d += 32) {
        float xv = xr[d];
        const float4* w = reinterpret_cast<const float4*>(Wg + (size_t)d * E_EXP);
        float4 wa = w[0], wb = w[1];
        acc[0] = fmaf(xv, wa.x, acc[0]);
        acc[1] = fmaf(xv, wa.y, acc[1]);
        acc[2] = fmaf(xv, wa.z, acc[2]);
        acc[3] = fmaf(xv, wa.w, acc[3]);
        acc[4] = fmaf(xv, wb.x, acc[4]);
        acc[5] = fmaf(xv, wb.y, acc[5]);
        acc[6] = fmaf(xv, wb.z, acc[6]);
        acc[7] = fmaf(xv, wb.w, acc[7]);
    }
#pragma unroll
    for (int e = 0; e < E_EXP; e++)
#pragma unroll
        for (int off = 16; off; off >>= 1)
            acc[e] += __shfl_xor_sync(0xffffffffu, acc[e], off);

    if (lane == 0) {
        float l[E_EXP];
#pragma unroll
        for (int e = 0; e < E_EXP; e++) l[e] = acc[e] + bg[e];
        float m = l[0];
#pragma unroll
        for (int e = 1; e < E_EXP; e++) m = fmaxf(m, l[e]);
        float s = 0.f;
#pragma unroll
        for (int e = 0; e < E_EXP; e++) { l[e] = expf(l[e] - m); s += l[e]; }
        float inv = 1.f / s;

        int i0 = 0;
#pragma unroll
        for (int e = 1; e < E_EXP; e++) if (l[e] > l[i0]) i0 = e;
        int i1 = (i0 == 0) ? 1 : 0;
#pragma unroll
        for (int e = 0; e < E_EXP; e++)
            if (e != i0 && l[e] > l[i1]) i1 = e;

        g_topi[2 * t + 0] = i0;  g_topw[2 * t + 0] = l[i0] * inv;
        g_topi[2 * t + 1] = i1;  g_topw[2 * t + 1] = l[i1] * inv;
        atomicAdd(&g_counts[i0], 1);
        atomicAdd(&g_counts[i1], 1);
    }
}

// ---------------- scan: 128-padded segment offsets + tile->expert map ------
__global__ void scan_kernel() {
    if (threadIdx.x == 0) {
        int o = 0;
        for (int e = 0; e < E_EXP; e++) {
            g_offp[e] = o;
            o += ((g_counts[e] + BM - 1) / BM) * BM;
        }
        g_offp[E_EXP] = o;
    }
    __syncthreads();
    for (int m = threadIdx.x; m < MAX_TILES; m += blockDim.x) {
        int s = m * BM, e = -1;
        for (int i = 0; i < E_EXP; i++)
            if (s >= g_offp[i] && s < g_offp[i + 1]) e = i;
        g_tile_expert[m] = e;
    }
}

// ---------------- scatter: token -> per-expert slot ------------------------
__global__ void scatter_kernel() {
    int t = blockIdx.x * blockDim.x + threadIdx.x;
    if (t >= T_TOK) return;
#pragma unroll
    for (int k = 0; k < 2; k++) {
        int e    = g_topi[2 * t + k];
        int pos  = atomicAdd(&g_cursor[e], 1);
        int slot = g_offp[e] + pos;
        g_tok[slot] = t;
        g_slotof[2 * t + k] = slot;
    }
}

// ---------------- GEMM: 128x128x8 tile, 256 threads, 8x8 microtile ---------
// PHASE 1: C=g_h = gelu( gather(x) @ W1[e] + b1[e] ),  K=1024, N=4096
// PHASE 2: C=g_y =        g_h      @ W2[e] + b2[e]  ,  K=4096, N=1024
template <int PHASE>
__global__ void __launch_bounds__(256, 2) gemm_kernel(
    const float* __restrict__ Xin,
    const float* __restrict__ Bw,
    const float* __restrict__ bias) {

    constexpr int K = (PHASE == 1) ? D_DIM : H_DIM;
    constexpr int N = (PHASE == 1) ? H_DIM : D_DIM;
    constexpr bool GATHER = (PHASE == 1);
    constexpr bool GELU   = (PHASE == 1);

    int mt = blockIdx.y;
    int e  = g_tile_expert[mt];
    if (e < 0) return;
    int m0 = mt * BM;
    int n0 = blockIdx.x * 128;

    const float* A  = (PHASE == 1) ? Xin : g_h;
    float*       C  = (PHASE == 1) ? g_h : g_y;
    const float* Be = Bw  + (size_t)e * K * N;
    const float* be = bias + (size_t)e * N;

    __shared__ float As[2][8][BM + 4];
    __shared__ float Bs[2][8][128];

    int tid = threadIdx.x;
    int ar = tid >> 1, ak = (tid & 1) * 4;          // A loader: row, k-quad
    int bk = tid >> 5, bn = (tid & 31) * 4;          // B loader: k-row, n-quad

    const float* arow;
    if (GATHER) {
        int tok = g_tok[m0 + ar];
        arow = (tok >= 0) ? (A + (size_t)tok * K) : nullptr;
    } else {
        arow = A + (size_t)(m0 + ar) * K;
    }
    const float* bptr = Be + (size_t)bk * N + n0 + bn;

    // preload tile 0
    {
        float4 av = arow ? *(const float4*)(arow + ak) : make_float4(0, 0, 0, 0);
        float4 bv = *(const float4*)(bptr);
        As[0][ak + 0][ar] = av.x; As[0][ak + 1][ar] = av.y;
        As[0][ak + 2][ar] = av.z; As[0][ak + 3][ar] = av.w;
        *(float4*)&Bs[0][bk][bn] = bv;
    }
    __syncthreads();

    int ty = tid >> 4, tx = tid & 15;
    int crow = ty * 8, ccol = tx * 8;

    float c[8][8];
#pragma unroll
    for (int i = 0; i < 8; i++)
#pragma unroll
        for (int j = 0; j < 8; j++) c[i][j] = 0.f;

    constexpr int NT = K / 8;
    int buf = 0;
    for (int t = 0; t < NT; ++t) {
        float4 av2, bv2;
        bool more = (t + 1 < NT);
        if (more) {
            int k0 = (t + 1) * 8;
            av2 = arow ? *(const float4*)(arow + k0 + ak) : make_float4(0, 0, 0, 0);
            bv2 = *(const float4*)(bptr + (size_t)k0 * N);
        }
#pragma unroll
        for (int kk = 0; kk < 8; kk++) {
            float a[8], b[8];
            *(float4*)&a[0] = *(const float4*)&As[buf][kk][crow];
            *(float4*)&a[4] = *(const float4*)&As[buf][kk][crow + 4];
            *(float4*)&b[0] = *(const float4*)&Bs[buf][kk][ccol];
            *(float4*)&b[4] = *(const float4*)&Bs[buf][kk][ccol + 4];
#pragma unroll
            for (int i = 0; i < 8; i++)
#pragma unroll
                for (int j = 0; j < 8; j++)
                    c[i][j] = fmaf(a[i], b[j], c[i][j]);
        }
        if (more) {
            int nb = buf ^ 1;
            As[nb][ak + 0][ar] = av2.x; As[nb][ak + 1][ar] = av2.y;
            As[nb][ak + 2][ar] = av2.z; As[nb][ak + 3][ar] = av2.w;
            *(float4*)&Bs[nb][bk][bn] = bv2;
            __syncthreads();
            buf = nb;
        }
    }

    // epilogue
    float bv[8];
#pragma unroll
    for (int j = 0; j < 8; j++) bv[j] = be[n0 + ccol + j];

#pragma unroll
    for (int i = 0; i < 8; i++) {
        size_t r = (size_t)(m0 + crow + i) * N + n0 + ccol;
        float v[8];
#pragma unroll
        for (int j = 0; j < 8; j++) {
            float u = c[i][j] + bv[j];
            if (GELU) u = 0.5f * u * (1.0f + erff(u * 0.7071067811865476f));
            v[j] = u;
        }
        *(float4*)&C[r]     = make_float4(v[0], v[1], v[2], v[3]);
        *(float4*)&C[r + 4] = make_float4(v[4], v[5], v[6], v[7]);
    }
}

// ---------------- combine: out[t] = w0*y[s0] + w1*y[s1]  (deterministic) ---
__global__ void combine_kernel(float* __restrict__ out) {
    int i = blockIdx.x * blockDim.x + threadIdx.x;        // over T*D/4
    constexpr int Q = D_DIM / 4;
    if (i >= T_TOK * Q) return;
    int t = i / Q, q = i - t * Q;
    int s0 = g_slotof[2 * t + 0], s1 = g_slotof[2 * t + 1];
    float w0 = g_topw[2 * t + 0], w1 = g_topw[2 * t + 1];
    const float4* y4 = reinterpret_cast<const float4*>(g_y);
    float4 a = y4[(size_t)s0 * Q + q];
    float4 b = y4[(size_t)s1 * Q + q];
    reinterpret_cast<float4*>(out)[i] =
        make_float4(fmaf(w0, a.x, w1 * b.x), fmaf(w0, a.y, w1 * b.y),
                    fmaf(w0, a.z, w1 * b.z), fmaf(w0, a.w, w1 * b.w));
}

// ---------------- launch ---------------------------------------------------
extern "C" void kernel_launch(void* const* d_in, const int* in_sizes, int n_in,
                              void* d_out, int out_size) {
    const float* x  = (const float*)d_in[0];
    const float* Wg = (const float*)d_in[1];
    const float* bg = (const float*)d_in[2];
    const float* W1 = (const float*)d_in[3];
    const float* b1 = (const float*)d_in[4];
    const float* W2 = (const float*)d_in[5];
    const float* b2 = (const float*)d_in[6];
    float* out = (float*)d_out;

    init_kernel<<<(MAX_SLOTS + 255) / 256, 256>>>();
    router_kernel<<<T_TOK / 8, 256>>>(x, Wg, bg);
    scan_kernel<<<1, 256>>>();
    scatter_kernel<<<T_TOK / 256, 256>>>();
    gemm_kernel<1><<<dim3(H_DIM / 128, MAX_TILES), 256>>>(x, W1, b1);
    gemm_kernel<2><<<dim3(D_DIM / 128, MAX_TILES), 256>>>(x, W2, b2);
    combine_kernel<<<(T_TOK * (D_DIM / 4) + 255) / 256, 256>>>(out);
}

// round 7
// speedup vs baseline: 1.8836x; 1.8836x over previous
#include <cuda_runtime.h>
#include <cuda_bf16.h>
#include <math.h>
#include <stdint.h>

#define T_TOK   8192
#define D_DIM   1024
#define E_EXP   8
#define H_DIM   4096
#define BM      128
#define MAX_TILES (2 * T_TOK / BM + E_EXP)     // 136
#define MAX_SLOTS (MAX_TILES * BM)             // 17408

// ---------------- scratch (static device globals) --------------------------
__device__ int   g_counts[E_EXP];
__device__ int   g_cursor[E_EXP];
__device__ int   g_offp[E_EXP + 1];
__device__ int   g_tile_expert[MAX_TILES];
__device__ int   g_tok[MAX_SLOTS];
__device__ int   g_slotof[T_TOK * 2];
__device__ int   g_topi[T_TOK * 2];
__device__ float g_topw[T_TOK * 2];

// split-precision bf16 weights, transposed to [E][N][K] (K contiguous)
__device__ __nv_bfloat16 g_w1h[(size_t)E_EXP * H_DIM * D_DIM];
__device__ __nv_bfloat16 g_w1l[(size_t)E_EXP * H_DIM * D_DIM];
__device__ __nv_bfloat16 g_w2h[(size_t)E_EXP * D_DIM * H_DIM];
__device__ __nv_bfloat16 g_w2l[(size_t)E_EXP * D_DIM * H_DIM];
// split x
__device__ __nv_bfloat16 g_xh[(size_t)T_TOK * D_DIM];
__device__ __nv_bfloat16 g_xl[(size_t)T_TOK * D_DIM];
// hidden activations, split
__device__ __nv_bfloat16 g_hh[(size_t)MAX_SLOTS * H_DIM];
__device__ __nv_bfloat16 g_hl[(size_t)MAX_SLOTS * H_DIM];
__device__ float g_y[(size_t)MAX_SLOTS * D_DIM];

// ---------------- helpers --------------------------------------------------
__device__ __forceinline__ uint32_t s2u(const void* p) {
    uint32_t a;
    asm("{ .reg .u64 t; cvta.to.shared.u64 t, %1; cvt.u32.u64 %0, t; }"
        : "=r"(a) : "l"(p));
    return a;
}
__device__ __forceinline__ void cpa16(uint32_t dst, const void* src) {
    asm volatile("cp.async.cg.shared.global [%0], [%1], 16;"
                 :: "r"(dst), "l"(src) : "memory");
}
#define CP_COMMIT() asm volatile("cp.async.commit_group;" ::: "memory")
#define CP_WAIT1()  asm volatile("cp.async.wait_group 1;" ::: "memory")

#define LDSM4(r0, r1, r2, r3, addr)                                         \
    asm volatile("ldmatrix.sync.aligned.m8n8.x4.shared.b16 {%0,%1,%2,%3},[%4];" \
                 : "=r"(r0), "=r"(r1), "=r"(r2), "=r"(r3) : "r"(addr))

__device__ __forceinline__ void mma16816(float* c, const uint32_t* a,
                                         const uint32_t* b) {
    asm volatile(
        "mma.sync.aligned.m16n8k16.row.col.f32.bf16.bf16.f32 "
        "{%0,%1,%2,%3},{%4,%5,%6,%7},{%8,%9},{%0,%1,%2,%3};"
        : "+f"(c[0]), "+f"(c[1]), "+f"(c[2]), "+f"(c[3])
        : "r"(a[0]), "r"(a[1]), "r"(a[2]), "r"(a[3]), "r"(b[0]), "r"(b[1]));
}

// smem layout: 2 stages x 32KB, then bias, then token indices
#define OFF_AH   0
#define OFF_AL   8192
#define OFF_BH   16384
#define OFF_BL   24576
#define STAGE_B  32768
#define OFF_BIAS 65536
#define OFF_TOK  66048
#define SMEM_REQ (66560 + 128)

// ---------------- init -----------------------------------------------------
__global__ void init_kernel() {
    int i = blockIdx.x * blockDim.x + threadIdx.x;
    if (i < E_EXP) { g_counts[i] = 0; g_cursor[i] = 0; }
    if (i < MAX_SLOTS) g_tok[i] = -1;
}

// ---------------- router ---------------------------------------------------
__global__ void router_kernel(const float* __restrict__ x,
                              const float* __restrict__ Wg,
                              const float* __restrict__ bg) {
    int t    = (blockIdx.x * blockDim.x + threadIdx.x) >> 5;
    int lane = threadIdx.x & 31;
    if (t >= T_TOK) return;
    const float* xr = x + (size_t)t * D_DIM;

    float acc[E_EXP];
#pragma unroll
    for (int e = 0; e < E_EXP; e++) acc[e] = 0.f;
    for (int d = lane; d < D_DIM; d += 32) {
        float xv = xr[d];
        const float4* w = reinterpret_cast<const float4*>(Wg + (size_t)d * E_EXP);
        float4 wa = w[0], wb = w[1];
        acc[0] = fmaf(xv, wa.x, acc[0]); acc[1] = fmaf(xv, wa.y, acc[1]);
        acc[2] = fmaf(xv, wa.z, acc[2]); acc[3] = fmaf(xv, wa.w, acc[3]);
        acc[4] = fmaf(xv, wb.x, acc[4]); acc[5] = fmaf(xv, wb.y, acc[5]);
        acc[6] = fmaf(xv, wb.z, acc[6]); acc[7] = fmaf(xv, wb.w, acc[7]);
    }
#pragma unroll
    for (int e = 0; e < E_EXP; e++)
#pragma unroll
        for (int off = 16; off; off >>= 1)
            acc[e] += __shfl_xor_sync(0xffffffffu, acc[e], off);

    if (lane == 0) {
        float l[E_EXP];
#pragma unroll
        for (int e = 0; e < E_EXP; e++) l[e] = acc[e] + bg[e];
        float m = l[0];
#pragma unroll
        for (int e = 1; e < E_EXP; e++) m = fmaxf(m, l[e]);
        float s = 0.f;
#pragma unroll
        for (int e = 0; e < E_EXP; e++) { l[e] = expf(l[e] - m); s += l[e]; }
        float inv = 1.f / s;
        int i0 = 0;
#pragma unroll
        for (int e = 1; e < E_EXP; e++) if (l[e] > l[i0]) i0 = e;
        int i1 = (i0 == 0) ? 1 : 0;
#pragma unroll
        for (int e = 0; e < E_EXP; e++)
            if (e != i0 && l[e] > l[i1]) i1 = e;
        g_topi[2 * t + 0] = i0;  g_topw[2 * t + 0] = l[i0] * inv;
        g_topi[2 * t + 1] = i1;  g_topw[2 * t + 1] = l[i1] * inv;
        atomicAdd(&g_counts[i0], 1);
        atomicAdd(&g_counts[i1], 1);
    }
}

// ---------------- scan -----------------------------------------------------
__global__ void scan_kernel() {
    if (threadIdx.x == 0) {
        int o = 0;
        for (int e = 0; e < E_EXP; e++) {
            g_offp[e] = o;
            o += ((g_counts[e] + BM - 1) / BM) * BM;
        }
        g_offp[E_EXP] = o;
    }
    __syncthreads();
    for (int m = threadIdx.x; m < MAX_TILES; m += blockDim.x) {
        int s = m * BM, e = -1;
        for (int i = 0; i < E_EXP; i++)
            if (s >= g_offp[i] && s < g_offp[i + 1]) e = i;
        g_tile_expert[m] = e;
    }
}

// ---------------- scatter --------------------------------------------------
__global__ void scatter_kernel() {
    int t = blockIdx.x * blockDim.x + threadIdx.x;
    if (t >= T_TOK) return;
#pragma unroll
    for (int k = 0; k < 2; k++) {
        int e    = g_topi[2 * t + k];
        int pos  = atomicAdd(&g_cursor[e], 1);
        int slot = g_offp[e] + pos;
        g_tok[slot] = t;
        g_slotof[2 * t + k] = slot;
    }
}

// ---------------- weight transpose + hi/lo split ---------------------------
__global__ void wsplit_kernel(const float* __restrict__ W1,
                              const float* __restrict__ W2) {
    __shared__ float t[32][33];
    int b = blockIdx.x;
    const float* W; __nv_bfloat16 *oh, *ol; int K, N, e, nt, kt;
    if (b < 32768) {
        W = W1; oh = g_w1h; ol = g_w1l; K = D_DIM; N = H_DIM;
        e = b >> 12; int r = b & 4095; nt = r & 127; kt = r >> 7;
    } else {
        int b2 = b - 32768;
        W = W2; oh = g_w2h; ol = g_w2l; K = H_DIM; N = D_DIM;
        e = b2 >> 12; int r = b2 & 4095; nt = r & 31; kt = r >> 5;
    }
    int n0 = nt * 32, k0 = kt * 32;
    int tx = threadIdx.x, ty = threadIdx.y;
    const float* We = W + (size_t)e * K * N;
#pragma unroll
    for (int i = 0; i < 32; i += 8)
        t[ty + i][tx] = We[(size_t)(k0 + ty + i) * N + n0 + tx];
    __syncthreads();
    __nv_bfloat16* ohe = oh + (size_t)e * K * N;
    __nv_bfloat16* ole = ol + (size_t)e * K * N;
#pragma unroll
    for (int i = 0; i < 32; i += 8) {
        float v = t[tx][ty + i];
        __nv_bfloat16 hb = __float2bfloat16(v);
        __nv_bfloat16 lb = __float2bfloat16(v - __bfloat162float(hb));
        size_t o = (size_t)(n0 + ty + i) * K + (k0 + tx);
        ohe[o] = hb; ole[o] = lb;
    }
}

// ---------------- x hi/lo split --------------------------------------------
__global__ void xsplit_kernel(const float* __restrict__ x) {
    int i = blockIdx.x * blockDim.x + threadIdx.x;     // over T*D/4
    float4 v = reinterpret_cast<const float4*>(x)[i];
    __nv_bfloat16 h0 = __float2bfloat16(v.x), h1 = __float2bfloat16(v.y);
    __nv_bfloat16 h2 = __float2bfloat16(v.z), h3 = __float2bfloat16(v.w);
    __nv_bfloat16 l0 = __float2bfloat16(v.x - __bfloat162float(h0));
    __nv_bfloat16 l1 = __float2bfloat16(v.y - __bfloat162float(h1));
    __nv_bfloat16 l2 = __float2bfloat16(v.z - __bfloat162float(h2));
    __nv_bfloat16 l3 = __float2bfloat16(v.w - __bfloat162float(h3));
    uint2 hp, lp;
    hp.x = (uint32_t)__bfloat16_as_ushort(h0) | ((uint32_t)__bfloat16_as_ushort(h1) << 16);
    hp.y = (uint32_t)__bfloat16_as_ushort(h2) | ((uint32_t)__bfloat16_as_ushort(h3) << 16);
    lp.x = (uint32_t)__bfloat16_as_ushort(l0) | ((uint32_t)__bfloat16_as_ushort(l1) << 16);
    lp.y = (uint32_t)__bfloat16_as_ushort(l2) | ((uint32_t)__bfloat16_as_ushort(l3) << 16);
    reinterpret_cast<uint2*>(g_xh)[i] = hp;
    reinterpret_cast<uint2*>(g_xl)[i] = lp;
}

// ---------------- HMMA GEMM ------------------------------------------------
// PHASE 1: h = gelu( gather(xh+xl) @ W1t[e]^T + b1 ) -> g_hh/g_hl
// PHASE 2: y =        (hh+hl)      @ W2t[e]^T + b2   -> g_y
// 128x128 tile, 256 thr, warp 32x64, k-chunk 32, split-bf16 3-product.
template <int PHASE>
__global__ void __launch_bounds__(256, 2) gemm_mma(const float* __restrict__ bias) {
    constexpr int K  = (PHASE == 1) ? D_DIM : H_DIM;
    constexpr int N  = (PHASE == 1) ? H_DIM : D_DIM;
    constexpr int NC = K / 32;

    int mt_blk = blockIdx.y;
    int e = g_tile_expert[mt_blk];
    if (e < 0) return;
    int m0 = mt_blk * BM, n0 = blockIdx.x * 128;

    extern __shared__ char dyn_smem[];
    char* sm = (char*)(((uintptr_t)dyn_smem + 127) & ~(uintptr_t)127);
    uint32_t sb = s2u(sm);

    int tid  = threadIdx.x;
    int lane = tid & 31, wid = tid >> 5;
    int wm = wid >> 1, wn = wid & 1;

    float* bias_s = (float*)(sm + OFF_BIAS);
    int*   tok_s  = (int*)(sm + OFF_TOK);

    if (tid < 128) {
        bias_s[tid] = bias[(size_t)e * N + n0 + tid];
        if (PHASE == 1) {
            int tk = g_tok[m0 + tid];
            tok_s[tid] = (tk < 0) ? 0 : tk;
        } else {
            tok_s[tid] = m0 + tid;
        }
    }
    __syncthreads();

    const __nv_bfloat16* Ah_g = (PHASE == 1) ? g_xh : g_hh;
    const __nv_bfloat16* Al_g = (PHASE == 1) ? g_xl : g_hl;
    const __nv_bfloat16* Bh_g = ((PHASE == 1) ? g_w1h : g_w2h) + ((size_t)e * N + n0) * K;
    const __nv_bfloat16* Bl_g = ((PHASE == 1) ? g_w1l : g_w2l) + ((size_t)e * N + n0) * K;

    // precompute ldmatrix lane offsets
    int q = lane >> 3, r = lane & 7;
    uint32_t aoff[2], boff[4];
#pragma unroll
    for (int mt = 0; mt < 2; mt++) {
        int rowA = wm * 32 + mt * 16 + (q & 1) * 8 + r;
        aoff[mt] = rowA * 32 + ((((uint32_t)(q >> 1)) ^ ((rowA >> 2) & 1)) << 4);
    }
#pragma unroll
    for (int j = 0; j < 4; j++) {
        int rowB = wn * 64 + j * 16 + (q >> 1) * 8 + r;
        boff[j] = rowB * 32 + ((((uint32_t)(q & 1)) ^ ((rowB >> 2) & 1)) << 4);
    }

    float acc[2][8][4];
#pragma unroll
    for (int a = 0; a < 2; a++)
#pragma unroll
        for (int b = 0; b < 8; b++)
#pragma unroll
            for (int c = 0; c < 4; c++) acc[a][b][c] = 0.f;

    // stage loader: 2 x 16B per array per thread
    auto load_stage = [&](int c) {
        if (c < NC) {
            int k0 = c * 32;
            uint32_t sbs = sb + (c & 1) * STAGE_B;
#pragma unroll
            for (int i = 0; i < 2; i++) {
                int t = tid * 2 + i;
                int slice = t >> 8, row = (t >> 1) & 127, chunk = t & 1;
                uint32_t soff = slice * 4096 + row * 32 +
                                (((uint32_t)chunk ^ ((row >> 2) & 1)) << 4);
                int kk = k0 + slice * 16 + chunk * 8;
                size_t arow = (size_t)tok_s[row] * K + kk;
                size_t brow = (size_t)row * K + kk;
                cpa16(sbs + OFF_AH + soff, Ah_g + arow);
                cpa16(sbs + OFF_AL + soff, Al_g + arow);
                cpa16(sbs + OFF_BH + soff, Bh_g + brow);
                cpa16(sbs + OFF_BL + soff, Bl_g + brow);
            }
        }
        CP_COMMIT();
    };

    load_stage(0);
    load_stage(1);

    for (int c = 0; c < NC; ++c) {
        CP_WAIT1();
        __syncthreads();
        uint32_t sbs = sb + (c & 1) * STAGE_B;
#pragma unroll
        for (int slice = 0; slice < 2; slice++) {
            uint32_t sl = sbs + slice * 4096;
            uint32_t ah[2][4], al[2][4];
#pragma unroll
            for (int mt = 0; mt < 2; mt++) {
                LDSM4(ah[mt][0], ah[mt][1], ah[mt][2], ah[mt][3], sl + OFF_AH + aoff[mt]);
                LDSM4(al[mt][0], al[mt][1], al[mt][2], al[mt][3], sl + OFF_AL + aoff[mt]);
            }
#pragma unroll
            for (int j = 0; j < 4; j++) {
                uint32_t bh[4], bl[4];
                LDSM4(bh[0], bh[1], bh[2], bh[3], sl + OFF_BH + boff[j]);
                LDSM4(bl[0], bl[1], bl[2], bl[3], sl + OFF_BL + boff[j]);
#pragma unroll
                for (int mt = 0; mt < 2; mt++) {
#pragma unroll
                    for (int jj = 0; jj < 2; jj++) {
                        int nt = j * 2 + jj;
                        mma16816(acc[mt][nt], ah[mt], bh + jj * 2);
                        mma16816(acc[mt][nt], ah[mt], bl + jj * 2);
                        mma16816(acc[mt][nt], al[mt], bh + jj * 2);
                    }
                }
            }
        }
        __syncthreads();
        load_stage(c + 2);
    }

    // ---------------- epilogue (registers -> global) ----------------
    int g = lane >> 2, tc = lane & 3;
#pragma unroll
    for (int mt = 0; mt < 2; mt++) {
        int rowb = m0 + wm * 32 + mt * 16 + g;
#pragma unroll
        for (int h = 0; h < 2; h++) {
            int row = rowb + h * 8;
            size_t base = (size_t)row * N + n0 + wn * 64 + tc * 2;
#pragma unroll
            for (int nt = 0; nt < 8; nt++) {
                int nb = wn * 64 + nt * 8 + tc * 2;
                float u0 = acc[mt][nt][h * 2 + 0] + bias_s[nb];
                float u1 = acc[mt][nt][h * 2 + 1] + bias_s[nb + 1];
                if (PHASE == 1) {
                    u0 = 0.5f * u0 * (1.0f + erff(u0 * 0.7071067811865476f));
                    u1 = 0.5f * u1 * (1.0f + erff(u1 * 0.7071067811865476f));
                    __nv_bfloat16 h0 = __float2bfloat16(u0);
                    __nv_bfloat16 h1 = __float2bfloat16(u1);
                    __nv_bfloat16 l0 = __float2bfloat16(u0 - __bfloat162float(h0));
                    __nv_bfloat16 l1 = __float2bfloat16(u1 - __bfloat162float(h1));
                    uint32_t hp = (uint32_t)__bfloat16_as_ushort(h0) |
                                  ((uint32_t)__bfloat16_as_ushort(h1) << 16);
                    uint32_t lp = (uint32_t)__bfloat16_as_ushort(l0) |
                                  ((uint32_t)__bfloat16_as_ushort(l1) << 16);
                    *(uint32_t*)(g_hh + base + nt * 8) = hp;
                    *(uint32_t*)(g_hl + base + nt * 8) = lp;
                } else {
                    float2 v = make_float2(u0, u1);
                    *(float2*)(g_y + base + nt * 8) = v;
                }
            }
        }
    }
}

// ---------------- combine --------------------------------------------------
__global__ void combine_kernel(float* __restrict__ out) {
    int i = blockIdx.x * blockDim.x + threadIdx.x;
    constexpr int Q = D_DIM / 4;
    if (i >= T_TOK * Q) return;
    int t = i / Q, qq = i - t * Q;
    int s0 = g_slotof[2 * t + 0], s1 = g_slotof[2 * t + 1];
    float w0 = g_topw[2 * t + 0], w1 = g_topw[2 * t + 1];
    const float4* y4 = reinterpret_cast<const float4*>(g_y);
    float4 a = y4[(size_t)s0 * Q + qq];
    float4 b = y4[(size_t)s1 * Q + qq];
    reinterpret_cast<float4*>(out)[i] =
        make_float4(fmaf(w0, a.x, w1 * b.x), fmaf(w0, a.y, w1 * b.y),
                    fmaf(w0, a.z, w1 * b.z), fmaf(w0, a.w, w1 * b.w));
}

// ---------------- launch ---------------------------------------------------
extern "C" void kernel_launch(void* const* d_in, const int* in_sizes, int n_in,
                              void* d_out, int out_size) {
    const float* x  = (const float*)d_in[0];
    const float* Wg = (const float*)d_in[1];
    const float* bg = (const float*)d_in[2];
    const float* W1 = (const float*)d_in[3];
    const float* b1 = (const float*)d_in[4];
    const float* W2 = (const float*)d_in[5];
    const float* b2 = (const float*)d_in[6];
    float* out = (float*)d_out;

    cudaFuncSetAttribute(gemm_mma<1>, cudaFuncAttributeMaxDynamicSharedMemorySize, SMEM_REQ);
    cudaFuncSetAttribute(gemm_mma<2>, cudaFuncAttributeMaxDynamicSharedMemorySize, SMEM_REQ);

    init_kernel<<<(MAX_SLOTS + 255) / 256, 256>>>();
    router_kernel<<<T_TOK / 8, 256>>>(x, Wg, bg);
    scan_kernel<<<1, 256>>>();
    scatter_kernel<<<T_TOK / 256, 256>>>();
    wsplit_kernel<<<65536, dim3(32, 8)>>>(W1, W2);
    xsplit_kernel<<<T_TOK * D_DIM / 4 / 256, 256>>>(x);
    gemm_mma<1><<<dim3(H_DIM / 128, MAX_TILES), 256, SMEM_REQ>>>(b1);
    gemm_mma<2><<<dim3(D_DIM / 128, MAX_TILES), 256, SMEM_REQ>>>(b2);
    combine_kernel<<<(T_TOK * (D_DIM / 4) + 255) / 256, 256>>>(out);
}

// round 8
// speedup vs baseline: 2.7058x; 1.4365x over previous
#include <cuda_runtime.h>
#include <cuda_bf16.h>
#include <cuda_fp16.h>
#include <math.h>
#include <stdint.h>

#define T_TOK   8192
#define D_DIM   1024
#define E_EXP   8
#define H_DIM   4096
#define BM      128
#define MAX_TILES (2 * T_TOK / BM + E_EXP)     // 136
#define MAX_SLOTS (MAX_TILES * BM)             // 17408

// ---------------- scratch (static device globals) --------------------------
__device__ int   g_counts[E_EXP];
__device__ int   g_cursor[E_EXP];
__device__ int   g_offp[E_EXP + 1];
__device__ int   g_tile_expert[MAX_TILES];
__device__ int   g_tok[MAX_SLOTS];
__device__ int   g_slotof[T_TOK * 2];
__device__ int   g_topi[T_TOK * 2];
__device__ float g_topw[T_TOK * 2];

// split-precision fp16 weights, transposed to [E][N][K] (K contiguous)
__device__ __half g_w1h[(size_t)E_EXP * H_DIM * D_DIM];
__device__ __half g_w1l[(size_t)E_EXP * H_DIM * D_DIM];
__device__ __half g_w2h[(size_t)E_EXP * D_DIM * H_DIM];
__device__ __half g_w2l[(size_t)E_EXP * D_DIM * H_DIM];
// single-fp16 activations
__device__ __half g_x16[(size_t)T_TOK * D_DIM];
__device__ __half g_h16[(size_t)MAX_SLOTS * H_DIM];
__device__ float  g_y[(size_t)MAX_SLOTS * D_DIM];

// ---------------- helpers --------------------------------------------------
__device__ __forceinline__ uint32_t s2u(const void* p) {
    uint32_t a;
    asm("{ .reg .u64 t; cvta.to.shared.u64 t, %1; cvt.u32.u64 %0, t; }"
        : "=r"(a) : "l"(p));
    return a;
}
__device__ __forceinline__ void cpa16(uint32_t dst, const void* src) {
    asm volatile("cp.async.cg.shared.global [%0], [%1], 16;"
                 :: "r"(dst), "l"(src) : "memory");
}
#define CP_COMMIT()  asm volatile("cp.async.commit_group;" ::: "memory")
#define CP_WAITG(n)  asm volatile("cp.async.wait_group %0;" :: "n"(n) : "memory")

#define LDSM4(r0, r1, r2, r3, addr)                                         \
    asm volatile("ldmatrix.sync.aligned.m8n8.x4.shared.b16 {%0,%1,%2,%3},[%4];" \
                 : "=r"(r0), "=r"(r1), "=r"(r2), "=r"(r3) : "r"(addr))

__device__ __forceinline__ void mma16816(float* c, const uint32_t* a,
                                         const uint32_t* b) {
    asm volatile(
        "mma.sync.aligned.m16n8k16.row.col.f32.f16.f16.f32 "
        "{%0,%1,%2,%3},{%4,%5,%6,%7},{%8,%9},{%0,%1,%2,%3};"
        : "+f"(c[0]), "+f"(c[1]), "+f"(c[2]), "+f"(c[3])
        : "r"(a[0]), "r"(a[1]), "r"(a[2]), "r"(a[3]), "r"(b[0]), "r"(b[1]));
}

// smem: 3 stages x 24KB (A 8K | BH 8K | BL 8K), then bias, then token idx
#define OFF_A    0
#define OFF_BH   8192
#define OFF_BL   16384
#define STAGE_B  24576
#define OFF_BIAS 73728
#define OFF_TOK  74240
#define SMEM_REQ (74752 + 128)

// ---------------- init -----------------------------------------------------
__global__ void init_kernel() {
    int i = blockIdx.x * blockDim.x + threadIdx.x;
    if (i < E_EXP) { g_counts[i] = 0; g_cursor[i] = 0; }
    if (i < MAX_SLOTS) g_tok[i] = -1;
}

// ---------------- router ---------------------------------------------------
__global__ void router_kernel(const float* __restrict__ x,
                              const float* __restrict__ Wg,
                              const float* __restrict__ bg) {
    int t    = (blockIdx.x * blockDim.x + threadIdx.x) >> 5;
    int lane = threadIdx.x & 31;
    if (t >= T_TOK) return;
    const float* xr = x + (size_t)t * D_DIM;

    float acc[E_EXP];
#pragma unroll
    for (int e = 0; e < E_EXP; e++) acc[e] = 0.f;
    for (int d = lane; d < D_DIM; d += 32) {
        float xv = xr[d];
        const float4* w = reinterpret_cast<const float4*>(Wg + (size_t)d * E_EXP);
        float4 wa = w[0], wb = w[1];
        acc[0] = fmaf(xv, wa.x, acc[0]); acc[1] = fmaf(xv, wa.y, acc[1]);
        acc[2] = fmaf(xv, wa.z, acc[2]); acc[3] = fmaf(xv, wa.w, acc[3]);
        acc[4] = fmaf(xv, wb.x, acc[4]); acc[5] = fmaf(xv, wb.y, acc[5]);
        acc[6] = fmaf(xv, wb.z, acc[6]); acc[7] = fmaf(xv, wb.w, acc[7]);
    }
#pragma unroll
    for (int e = 0; e < E_EXP; e++)
#pragma unroll
        for (int off = 16; off; off >>= 1)
            acc[e] += __shfl_xor_sync(0xffffffffu, acc[e], off);

    if (lane == 0) {
        float l[E_EXP];
#pragma unroll
        for (int e = 0; e < E_EXP; e++) l[e] = acc[e] + bg[e];
        float m = l[0];
#pragma unroll
        for (int e = 1; e < E_EXP; e++) m = fmaxf(m, l[e]);
        float s = 0.f;
#pragma unroll
        for (int e = 0; e < E_EXP; e++) { l[e] = expf(l[e] - m); s += l[e]; }
        float inv = 1.f / s;
        int i0 = 0;
#pragma unroll
        for (int e = 1; e < E_EXP; e++) if (l[e] > l[i0]) i0 = e;
        int i1 = (i0 == 0) ? 1 : 0;
#pragma unroll
        for (int e = 0; e < E_EXP; e++)
            if (e != i0 && l[e] > l[i1]) i1 = e;
        g_topi[2 * t + 0] = i0;  g_topw[2 * t + 0] = l[i0] * inv;
        g_topi[2 * t + 1] = i1;  g_topw[2 * t + 1] = l[i1] * inv;
        atomicAdd(&g_counts[i0], 1);
        atomicAdd(&g_counts[i1], 1);
    }
}

// ---------------- scan -----------------------------------------------------
__global__ void scan_kernel() {
    if (threadIdx.x == 0) {
        int o = 0;
        for (int e = 0; e < E_EXP; e++) {
            g_offp[e] = o;
            o += ((g_counts[e] + BM - 1) / BM) * BM;
        }
        g_offp[E_EXP] = o;
    }
    __syncthreads();
    for (int m = threadIdx.x; m < MAX_TILES; m += blockDim.x) {
        int s = m * BM, e = -1;
        for (int i = 0; i < E_EXP; i++)
            if (s >= g_offp[i] && s < g_offp[i + 1]) e = i;
        g_tile_expert[m] = e;
    }
}

// ---------------- scatter --------------------------------------------------
__global__ void scatter_kernel() {
    int t = blockIdx.x * blockDim.x + threadIdx.x;
    if (t >= T_TOK) return;
#pragma unroll
    for (int k = 0; k < 2; k++) {
        int e    = g_topi[2 * t + k];
        int pos  = atomicAdd(&g_cursor[e], 1);
        int slot = g_offp[e] + pos;
        g_tok[slot] = t;
        g_slotof[2 * t + k] = slot;
    }
}

// ---------------- weight transpose + fp16 hi/lo split ----------------------
__global__ void wsplit_kernel(const float* __restrict__ W1,
                              const float* __restrict__ W2) {
    __shared__ float t[32][33];
    int b = blockIdx.x;
    const float* W; __half *oh, *ol; int K, N, e, nt, kt;
    if (b < 32768) {
        W = W1; oh = g_w1h; ol = g_w1l; K = D_DIM; N = H_DIM;
        e = b >> 12; int r = b & 4095; nt = r & 127; kt = r >> 7;
    } else {
        int b2 = b - 32768;
        W = W2; oh = g_w2h; ol = g_w2l; K = H_DIM; N = D_DIM;
        e = b2 >> 12; int r = b2 & 4095; nt = r & 31; kt = r >> 5;
    }
    int n0 = nt * 32, k0 = kt * 32;
    int tx = threadIdx.x, ty = threadIdx.y;
    const float* We = W + (size_t)e * K * N;
#pragma unroll
    for (int i = 0; i < 32; i += 8)
        t[ty + i][tx] = We[(size_t)(k0 + ty + i) * N + n0 + tx];
    __syncthreads();
    __half* ohe = oh + (size_t)e * K * N;
    __half* ole = ol + (size_t)e * K * N;
#pragma unroll
    for (int i = 0; i < 32; i += 8) {
        float v = t[tx][ty + i];
        __half hb = __float2half_rn(v);
        __half lb = __float2half_rn(v - __half2float(hb));
        size_t o = (size_t)(n0 + ty + i) * K + (k0 + tx);
        ohe[o] = hb; ole[o] = lb;
    }
}

// ---------------- x fp16 convert -------------------------------------------
__global__ void xsplit_kernel(const float* __restrict__ x) {
    int i = blockIdx.x * blockDim.x + threadIdx.x;     // over T*D/4
    float4 v = reinterpret_cast<const float4*>(x)[i];
    __half2 p0 = __floats2half2_rn(v.x, v.y);
    __half2 p1 = __floats2half2_rn(v.z, v.w);
    uint2 o;
    o.x = *(uint32_t*)&p0;
    o.y = *(uint32_t*)&p1;
    reinterpret_cast<uint2*>(g_x16)[i] = o;
}

// ---------------- HMMA GEMM (fp16 2-product split-weight) ------------------
// PHASE 1: h = gelu( gather(x16) @ (W1h+W1l)[e]^T + b1 ) -> g_h16
// PHASE 2: y =        h16        @ (W2h+W2l)[e]^T + b2   -> g_y
// 128x128 tile, 256 thr, warp 32x64, k-chunk 32, 3-stage cp.async ring.
template <int PHASE>
__global__ void __launch_bounds__(256, 2) gemm_mma(const float* __restrict__ bias) {
    constexpr int K  = (PHASE == 1) ? D_DIM : H_DIM;
    constexpr int N  = (PHASE == 1) ? H_DIM : D_DIM;
    constexpr int NC = K / 32;

    int mt_blk = blockIdx.y;
    int e = g_tile_expert[mt_blk];
    if (e < 0) return;
    int m0 = mt_blk * BM, n0 = blockIdx.x * 128;

    extern __shared__ char dyn_smem[];
    char* sm = (char*)(((uintptr_t)dyn_smem + 127) & ~(uintptr_t)127);
    uint32_t sb = s2u(sm);

    int tid  = threadIdx.x;
    int lane = tid & 31, wid = tid >> 5;
    int wm = wid >> 1, wn = wid & 1;

    float* bias_s = (float*)(sm + OFF_BIAS);
    int*   tok_s  = (int*)(sm + OFF_TOK);

    if (tid < 128) {
        bias_s[tid] = bias[(size_t)e * N + n0 + tid];
        if (PHASE == 1) {
            int tk = g_tok[m0 + tid];
            tok_s[tid] = (tk < 0) ? 0 : tk;
        } else {
            tok_s[tid] = m0 + tid;
        }
    }
    __syncthreads();

    const __half* A_g  = (PHASE == 1) ? g_x16 : g_h16;
    const __half* Bh_g = ((PHASE == 1) ? g_w1h : g_w2h) + ((size_t)e * N + n0) * K;
    const __half* Bl_g = ((PHASE == 1) ? g_w1l : g_w2l) + ((size_t)e * N + n0) * K;

    // ldmatrix lane offsets (32B rows, 16B-chunk XOR swizzle)
    int q = lane >> 3, r = lane & 7;
    uint32_t aoff[2], boff[4];
#pragma unroll
    for (int mt = 0; mt < 2; mt++) {
        int rowA = wm * 32 + mt * 16 + (q & 1) * 8 + r;
        aoff[mt] = rowA * 32 + ((((uint32_t)(q >> 1)) ^ ((rowA >> 2) & 1)) << 4);
    }
#pragma unroll
    for (int j = 0; j < 4; j++) {
        int rowB = wn * 64 + j * 16 + (q >> 1) * 8 + r;
        boff[j] = rowB * 32 + ((((uint32_t)(q & 1)) ^ ((rowB >> 2) & 1)) << 4);
    }

    float acc[2][8][4];
#pragma unroll
    for (int a = 0; a < 2; a++)
#pragma unroll
        for (int b = 0; b < 8; b++)
#pragma unroll
            for (int c = 0; c < 4; c++) acc[a][b][c] = 0.f;

    // stage loader: 2 x 16B per array per thread (A, BH, BL)
    auto load_stage = [&](int c) {
        if (c < NC) {
            int k0 = c * 32;
            uint32_t sbs = sb + (uint32_t)(c % 3) * STAGE_B;
#pragma unroll
            for (int i = 0; i < 2; i++) {
                int t = tid * 2 + i;
                int slice = t >> 8, row = (t >> 1) & 127, chunk = t & 1;
                uint32_t soff = slice * 4096 + row * 32 +
                                (((uint32_t)chunk ^ ((row >> 2) & 1)) << 4);
                int kk = k0 + slice * 16 + chunk * 8;
                size_t arow = (size_t)tok_s[row] * K + kk;
                size_t brow = (size_t)row * K + kk;
                cpa16(sbs + OFF_A  + soff, A_g  + arow);
                cpa16(sbs + OFF_BH + soff, Bh_g + brow);
                cpa16(sbs + OFF_BL + soff, Bl_g + brow);
            }
        }
        CP_COMMIT();
    };

    load_stage(0);
    load_stage(1);

    for (int c = 0; c < NC; ++c) {
        CP_WAITG(1);
        __syncthreads();
        load_stage(c + 2);                 // 2-deep prefetch into free ring slot
        uint32_t sbs = sb + (uint32_t)(c % 3) * STAGE_B;
#pragma unroll
        for (int slice = 0; slice < 2; slice++) {
            uint32_t sl = sbs + slice * 4096;
            uint32_t ah[2][4];
#pragma unroll
            for (int mt = 0; mt < 2; mt++)
                LDSM4(ah[mt][0], ah[mt][1], ah[mt][2], ah[mt][3], sl + OFF_A + aoff[mt]);
#pragma unroll
            for (int j = 0; j < 4; j++) {
                uint32_t bh[4], bl[4];
                LDSM4(bh[0], bh[1], bh[2], bh[3], sl + OFF_BH + boff[j]);
                LDSM4(bl[0], bl[1], bl[2], bl[3], sl + OFF_BL + boff[j]);
#pragma unroll
                for (int mt = 0; mt < 2; mt++) {
#pragma unroll
                    for (int jj = 0; jj < 2; jj++) {
                        int nt = j * 2 + jj;
                        mma16816(acc[mt][nt], ah[mt], bh + jj * 2);
                        mma16816(acc[mt][nt], ah[mt], bl + jj * 2);
                    }
                }
            }
        }
    }

    // ---------------- epilogue (registers -> global) ----------------
    int g = lane >> 2, tc = lane & 3;
#pragma unroll
    for (int mt = 0; mt < 2; mt++) {
        int rowb = m0 + wm * 32 + mt * 16 + g;
#pragma unroll
        for (int h = 0; h < 2; h++) {
            int row = rowb + h * 8;
            size_t base = (size_t)row * N + n0 + wn * 64 + tc * 2;
#pragma unroll
            for (int nt = 0; nt < 8; nt++) {
                int nb = wn * 64 + nt * 8 + tc * 2;
                float u0 = acc[mt][nt][h * 2 + 0] + bias_s[nb];
                float u1 = acc[mt][nt][h * 2 + 1] + bias_s[nb + 1];
                if (PHASE == 1) {
                    u0 = 0.5f * u0 * (1.0f + erff(u0 * 0.7071067811865476f));
                    u1 = 0.5f * u1 * (1.0f + erff(u1 * 0.7071067811865476f));
                    __half2 p = __floats2half2_rn(u0, u1);
                    *(uint32_t*)(g_h16 + base + nt * 8) = *(uint32_t*)&p;
                } else {
                    float2 v = make_float2(u0, u1);
                    *(float2*)(g_y + base + nt * 8) = v;
                }
            }
        }
    }
}

// ---------------- combine --------------------------------------------------
__global__ void combine_kernel(float* __restrict__ out) {
    int i = blockIdx.x * blockDim.x + threadIdx.x;
    constexpr int Q = D_DIM / 4;
    if (i >= T_TOK * Q) return;
    int t = i / Q, qq = i - t * Q;
    int s0 = g_slotof[2 * t + 0], s1 = g_slotof[2 * t + 1];
    float w0 = g_topw[2 * t + 0], w1 = g_topw[2 * t + 1];
    const float4* y4 = reinterpret_cast<const float4*>(g_y);
    float4 a = y4[(size_t)s0 * Q + qq];
    float4 b = y4[(size_t)s1 * Q + qq];
    reinterpret_cast<float4*>(out)[i] =
        make_float4(fmaf(w0, a.x, w1 * b.x), fmaf(w0, a.y, w1 * b.y),
                    fmaf(w0, a.z, w1 * b.z), fmaf(w0, a.w, w1 * b.w));
}

// ---------------- launch ---------------------------------------------------
extern "C" void kernel_launch(void* const* d_in, const int* in_sizes, int n_in,
                              void* d_out, int out_size) {
    const float* x  = (const float*)d_in[0];
    const float* Wg = (const float*)d_in[1];
    const float* bg = (const float*)d_in[2];
    const float* W1 = (const float*)d_in[3];
    const float* b1 = (const float*)d_in[4];
    const float* W2 = (const float*)d_in[5];
    const float* b2 = (const float*)d_in[6];
    float* out = (float*)d_out;

    cudaFuncSetAttribute(gemm_mma<1>, cudaFuncAttributeMaxDynamicSharedMemorySize, SMEM_REQ);
    cudaFuncSetAttribute(gemm_mma<2>, cudaFuncAttributeMaxDynamicSharedMemorySize, SMEM_REQ);

    init_kernel<<<(MAX_SLOTS + 255) / 256, 256>>>();
    router_kernel<<<T_TOK / 8, 256>>>(x, Wg, bg);
    scan_kernel<<<1, 256>>>();
    scatter_kernel<<<T_TOK / 256, 256>>>();
    wsplit_kernel<<<65536, dim3(32, 8)>>>(W1, W2);
    xsplit_kernel<<<T_TOK * D_DIM / 4 / 256, 256>>>(x);
    gemm_mma<1><<<dim3(H_DIM / 128, MAX_TILES), 256, SMEM_REQ>>>(b1);
    gemm_mma<2><<<dim3(D_DIM / 128, MAX_TILES), 256, SMEM_REQ>>>(b2);
    combine_kernel<<<(T_TOK * (D_DIM / 4) + 255) / 256, 256>>>(out);
}

// round 9
// speedup vs baseline: 7.4658x; 2.7592x over previous
#include <cuda_runtime.h>
#include <cuda_bf16.h>
#include <cuda_fp16.h>
#include <math.h>
#include <stdint.h>

#define T_TOK   8192
#define D_DIM   1024
#define E_EXP   8
#define H_DIM   4096
#define BM      128
#define MAX_TILES (2 * T_TOK / BM + E_EXP)     // 136
#define MAX_SLOTS (MAX_TILES * BM)             // 17408

// ---------------- scratch (static device globals) --------------------------
__device__ int   g_counts[E_EXP];
__device__ int   g_cursor[E_EXP];
__device__ int   g_offp[E_EXP + 1];
__device__ int   g_tile_expert[MAX_TILES];
__device__ int   g_tok[MAX_SLOTS];
__device__ int   g_slotof[T_TOK * 2];
__device__ int   g_topi[T_TOK * 2];
__device__ float g_topw[T_TOK * 2];

// fp16 weights, transposed to [E][N][K] (K contiguous)
__device__ __half g_w1[(size_t)E_EXP * H_DIM * D_DIM];
__device__ __half g_w2[(size_t)E_EXP * D_DIM * H_DIM];
// fp16 activations
__device__ __half g_x16[(size_t)T_TOK * D_DIM];
__device__ __half g_h16[(size_t)MAX_SLOTS * H_DIM];
__device__ float  g_y[(size_t)MAX_SLOTS * D_DIM];

// ---------------- helpers --------------------------------------------------
__device__ __forceinline__ uint32_t s2u(const void* p) {
    uint32_t a;
    asm("{ .reg .u64 t; cvta.to.shared.u64 t, %1; cvt.u32.u64 %0, t; }"
        : "=r"(a) : "l"(p));
    return a;
}
__device__ __forceinline__ void cpa16(uint32_t dst, const void* src) {
    asm volatile("cp.async.cg.shared.global [%0], [%1], 16;"
                 :: "r"(dst), "l"(src) : "memory");
}
#define CP_COMMIT()  asm volatile("cp.async.commit_group;" ::: "memory")
#define CP_WAITG(n)  asm volatile("cp.async.wait_group %0;" :: "n"(n) : "memory")

#define LDSM4(r0, r1, r2, r3, addr)                                         \
    asm volatile("ldmatrix.sync.aligned.m8n8.x4.shared.b16 {%0,%1,%2,%3},[%4];" \
                 : "=r"(r0), "=r"(r1), "=r"(r2), "=r"(r3) : "r"(addr))

__device__ __forceinline__ void mma16816(float* c, const uint32_t* a,
                                         const uint32_t* b) {
    asm volatile(
        "mma.sync.aligned.m16n8k16.row.col.f32.f16.f16.f32 "
        "{%0,%1,%2,%3},{%4,%5,%6,%7},{%8,%9},{%0,%1,%2,%3};"
        : "+f"(c[0]), "+f"(c[1]), "+f"(c[2]), "+f"(c[3])
        : "r"(a[0]), "r"(a[1]), "r"(a[2]), "r"(a[3]), "r"(b[0]), "r"(b[1]));
}

// smem: 3 stages x 32KB (A 16K | B 16K), then bias, then token idx
#define OFF_A    0
#define OFF_B    16384
#define STAGE_B  32768
#define OFF_BIAS 98304
#define OFF_TOK  98816
#define SMEM_REQ (99328 + 128)

// ---------------- init -----------------------------------------------------
__global__ void init_kernel() {
    int i = blockIdx.x * blockDim.x + threadIdx.x;
    if (i < E_EXP) { g_counts[i] = 0; g_cursor[i] = 0; }
    if (i < MAX_SLOTS) g_tok[i] = -1;
}

// ---------------- router ---------------------------------------------------
__global__ void router_kernel(const float* __restrict__ x,
                              const float* __restrict__ Wg,
                              const float* __restrict__ bg) {
    int t    = (blockIdx.x * blockDim.x + threadIdx.x) >> 5;
    int lane = threadIdx.x & 31;
    if (t >= T_TOK) return;
    const float* xr = x + (size_t)t * D_DIM;

    float acc[E_EXP];
#pragma unroll
    for (int e = 0; e < E_EXP; e++) acc[e] = 0.f;
    for (int d = lane; d < D_DIM; d += 32) {
        float xv = xr[d];
        const float4* w = reinterpret_cast<const float4*>(Wg + (size_t)d * E_EXP);
        float4 wa = w[0], wb = w[1];
        acc[0] = fmaf(xv, wa.x, acc[0]); acc[1] = fmaf(xv, wa.y, acc[1]);
        acc[2] = fmaf(xv, wa.z, acc[2]); acc[3] = fmaf(xv, wa.w, acc[3]);
        acc[4] = fmaf(xv, wb.x, acc[4]); acc[5] = fmaf(xv, wb.y, acc[5]);
        acc[6] = fmaf(xv, wb.z, acc[6]); acc[7] = fmaf(xv, wb.w, acc[7]);
    }
#pragma unroll
    for (int e = 0; e < E_EXP; e++)
#pragma unroll
        for (int off = 16; off; off >>= 1)
            acc[e] += __shfl_xor_sync(0xffffffffu, acc[e], off);

    if (lane == 0) {
        float l[E_EXP];
#pragma unroll
        for (int e = 0; e < E_EXP; e++) l[e] = acc[e] + bg[e];
        float m = l[0];
#pragma unroll
        for (int e = 1; e < E_EXP; e++) m = fmaxf(m, l[e]);
        float s = 0.f;
#pragma unroll
        for (int e = 0; e < E_EXP; e++) { l[e] = expf(l[e] - m); s += l[e]; }
        float inv = 1.f / s;
        int i0 = 0;
#pragma unroll
        for (int e = 1; e < E_EXP; e++) if (l[e] > l[i0]) i0 = e;
        int i1 = (i0 == 0) ? 1 : 0;
#pragma unroll
        for (int e = 0; e < E_EXP; e++)
            if (e != i0 && l[e] > l[i1]) i1 = e;
        g_topi[2 * t + 0] = i0;  g_topw[2 * t + 0] = l[i0] * inv;
        g_topi[2 * t + 1] = i1;  g_topw[2 * t + 1] = l[i1] * inv;
        atomicAdd(&g_counts[i0], 1);
        atomicAdd(&g_counts[i1], 1);
    }
}

// ---------------- scan -----------------------------------------------------
__global__ void scan_kernel() {
    if (threadIdx.x == 0) {
        int o = 0;
        for (int e = 0; e < E_EXP; e++) {
            g_offp[e] = o;
            o += ((g_counts[e] + BM - 1) / BM) * BM;
        }
        g_offp[E_EXP] = o;
    }
    __syncthreads();
    for (int m = threadIdx.x; m < MAX_TILES; m += blockDim.x) {
        int s = m * BM, e = -1;
        for (int i = 0; i < E_EXP; i++)
            if (s >= g_offp[i] && s < g_offp[i + 1]) e = i;
        g_tile_expert[m] = e;
    }
}

// ---------------- scatter --------------------------------------------------
__global__ void scatter_kernel() {
    int t = blockIdx.x * blockDim.x + threadIdx.x;
    if (t >= T_TOK) return;
#pragma unroll
    for (int k = 0; k < 2; k++) {
        int e    = g_topi[2 * t + k];
        int pos  = atomicAdd(&g_cursor[e], 1);
        int slot = g_offp[e] + pos;
        g_tok[slot] = t;
        g_slotof[2 * t + k] = slot;
    }
}

// ---------------- weight transpose + fp16 convert --------------------------
__global__ void wsplit_kernel(const float* __restrict__ W1,
                              const float* __restrict__ W2) {
    __shared__ float t[32][33];
    int b = blockIdx.x;
    const float* W; __half* oh; int K, N, e, nt, kt;
    if (b < 32768) {
        W = W1; oh = g_w1; K = D_DIM; N = H_DIM;
        e = b >> 12; int r = b & 4095; nt = r & 127; kt = r >> 7;
    } else {
        int b2 = b - 32768;
        W = W2; oh = g_w2; K = H_DIM; N = D_DIM;
        e = b2 >> 12; int r = b2 & 4095; nt = r & 31; kt = r >> 5;
    }
    int n0 = nt * 32, k0 = kt * 32;
    int tx = threadIdx.x, ty = threadIdx.y;
    const float* We = W + (size_t)e * K * N;
#pragma unroll
    for (int i = 0; i < 32; i += 8)
        t[ty + i][tx] = We[(size_t)(k0 + ty + i) * N + n0 + tx];
    __syncthreads();
    __half* ohe = oh + (size_t)e * K * N;
#pragma unroll
    for (int i = 0; i < 32; i += 8) {
        float v = t[tx][ty + i];
        ohe[(size_t)(n0 + ty + i) * K + (k0 + tx)] = __float2half_rn(v);
    }
}

// ---------------- x fp16 convert -------------------------------------------
__global__ void xsplit_kernel(const float* __restrict__ x) {
    int i = blockIdx.x * blockDim.x + threadIdx.x;     // over T*D/4
    float4 v = reinterpret_cast<const float4*>(x)[i];
    __half2 p0 = __floats2half2_rn(v.x, v.y);
    __half2 p1 = __floats2half2_rn(v.z, v.w);
    uint2 o;
    o.x = *(uint32_t*)&p0;
    o.y = *(uint32_t*)&p1;
    reinterpret_cast<uint2*>(g_x16)[i] = o;
}

// ---------------- HMMA GEMM (single fp16, k-chunk 64) ----------------------
// PHASE 1: h = gelu( gather(x16) @ W1[e]^T + b1 ) -> g_h16
// PHASE 2: y =        h16        @ W2[e]^T + b2   -> g_y
// 128x128 tile, 256 thr, warp 32x64, k-chunk 64, 3-stage cp.async ring.
template <int PHASE>
__global__ void __launch_bounds__(256, 2) gemm_mma(const float* __restrict__ bias) {
    constexpr int K  = (PHASE == 1) ? D_DIM : H_DIM;
    constexpr int N  = (PHASE == 1) ? H_DIM : D_DIM;
    constexpr int NC = K / 64;

    int mt_blk = blockIdx.y;
    int e = g_tile_expert[mt_blk];
    if (e < 0) return;
    int m0 = mt_blk * BM, n0 = blockIdx.x * 128;

    extern __shared__ char dyn_smem[];
    char* sm = (char*)(((uintptr_t)dyn_smem + 127) & ~(uintptr_t)127);
    uint32_t sb = s2u(sm);

    int tid  = threadIdx.x;
    int lane = tid & 31, wid = tid >> 5;
    int wm = wid >> 1, wn = wid & 1;

    float* bias_s = (float*)(sm + OFF_BIAS);
    int*   tok_s  = (int*)(sm + OFF_TOK);

    if (tid < 128) {
        bias_s[tid] = bias[(size_t)e * N + n0 + tid];
        if (PHASE == 1) {
            int tk = g_tok[m0 + tid];
            tok_s[tid] = (tk < 0) ? 0 : tk;
        } else {
            tok_s[tid] = m0 + tid;
        }
    }
    __syncthreads();

    const __half* A_g = (PHASE == 1) ? g_x16 : g_h16;
    const __half* B_g = ((PHASE == 1) ? g_w1 : g_w2) + ((size_t)e * N + n0) * K;

    // ldmatrix lane rows (128B rows, chunk ^ (row&7) swizzle)
    int q = lane >> 3, r = lane & 7;
    int rowA_[2], rowB_[4];
#pragma unroll
    for (int mt = 0; mt < 2; mt++)
        rowA_[mt] = wm * 32 + mt * 16 + (q & 1) * 8 + r;
#pragma unroll
    for (int j = 0; j < 4; j++)
        rowB_[j] = wn * 64 + j * 16 + (q >> 1) * 8 + r;
    int qhA = q >> 1;     // k-chunk select bit for A fragments
    int qhB = q & 1;      // k-chunk select bit for B fragments

    float acc[2][8][4];
#pragma unroll
    for (int a = 0; a < 2; a++)
#pragma unroll
        for (int b = 0; b < 8; b++)
#pragma unroll
            for (int c = 0; c < 4; c++) acc[a][b][c] = 0.f;

    // stage loader: 4 x 16B per array per thread (A, B); row=128B, 8 chunks
    auto load_stage = [&](int c) {
        if (c < NC) {
            int k0 = c * 64;
            uint32_t sbs = sb + (uint32_t)(c % 3) * STAGE_B;
#pragma unroll
            for (int i = 0; i < 4; i++) {
                int t = tid + i * 256;
                int row = t >> 3, chunk = t & 7;
                uint32_t soff = (uint32_t)row * 128 +
                                (((uint32_t)(chunk ^ (row & 7))) << 4);
                int kk = k0 + chunk * 8;
                cpa16(sbs + OFF_A + soff, A_g + (size_t)tok_s[row] * K + kk);
                cpa16(sbs + OFF_B + soff, B_g + (size_t)row * K + kk);
            }
        }
        CP_COMMIT();
    };

    load_stage(0);
    load_stage(1);

    for (int c = 0; c < NC; ++c) {
        CP_WAITG(1);
        __syncthreads();
        load_stage(c + 2);                 // 2-deep prefetch into free ring slot
        uint32_t sbs = sb + (uint32_t)(c % 3) * STAGE_B;
#pragma unroll
        for (int slice = 0; slice < 4; slice++) {
            uint32_t ah[2][4];
#pragma unroll
            for (int mt = 0; mt < 2; mt++) {
                int row = rowA_[mt];
                uint32_t off = (uint32_t)row * 128 +
                    (((uint32_t)((slice * 2 + qhA) ^ (row & 7))) << 4);
                LDSM4(ah[mt][0], ah[mt][1], ah[mt][2], ah[mt][3],
                      sbs + OFF_A + off);
            }
#pragma unroll
            for (int j = 0; j < 4; j++) {
                int row = rowB_[j];
                uint32_t off = (uint32_t)row * 128 +
                    (((uint32_t)((slice * 2 + qhB) ^ (row & 7))) << 4);
                uint32_t bh[4];
                LDSM4(bh[0], bh[1], bh[2], bh[3], sbs + OFF_B + off);
#pragma unroll
                for (int mt = 0; mt < 2; mt++) {
#pragma unroll
                    for (int jj = 0; jj < 2; jj++)
                        mma16816(acc[mt][j * 2 + jj], ah[mt], bh + jj * 2);
                }
            }
        }
    }

    // ---------------- epilogue (registers -> global) ----------------
    int g = lane >> 2, tc = lane & 3;
#pragma unroll
    for (int mt = 0; mt < 2; mt++) {
        int rowb = m0 + wm * 32 + mt * 16 + g;
#pragma unroll
        for (int h = 0; h < 2; h++) {
            int row = rowb + h * 8;
            size_t base = (size_t)row * N + n0 + wn * 64 + tc * 2;
#pragma unroll
            for (int nt = 0; nt < 8; nt++) {
                int nb = wn * 64 + nt * 8 + tc * 2;
                float u0 = acc[mt][nt][h * 2 + 0] + bias_s[nb];
                float u1 = acc[mt][nt][h * 2 + 1] + bias_s[nb + 1];
                if (PHASE == 1) {
                    u0 = 0.5f * u0 * (1.0f + erff(u0 * 0.7071067811865476f));
                    u1 = 0.5f * u1 * (1.0f + erff(u1 * 0.7071067811865476f));
                    __half2 p = __floats2half2_rn(u0, u1);
                    *(uint32_t*)(g_h16 + base + nt * 8) = *(uint32_t*)&p;
                } else {
                    float2 v = make_float2(u0, u1);
                    *(float2*)(g_y + base + nt * 8) = v;
                }
            }
        }
    }
}

// ---------------- combine --------------------------------------------------
__global__ void combine_kernel(float* __restrict__ out) {
    int i = blockIdx.x * blockDim.x + threadIdx.x;
    constexpr int Q = D_DIM / 4;
    if (i >= T_TOK * Q) return;
    int t = i / Q, qq = i - t * Q;
    int s0 = g_slotof[2 * t + 0], s1 = g_slotof[2 * t + 1];
    float w0 = g_topw[2 * t + 0], w1 = g_topw[2 * t + 1];
    const float4* y4 = reinterpret_cast<const float4*>(g_y);
    float4 a = y4[(size_t)s0 * Q + qq];
    float4 b = y4[(size_t)s1 * Q + qq];
    reinterpret_cast<float4*>(out)[i] =
        make_float4(fmaf(w0, a.x, w1 * b.x), fmaf(w0, a.y, w1 * b.y),
                    fmaf(w0, a.z, w1 * b.z), fmaf(w0, a.w, w1 * b.w));
}

// ---------------- launch ---------------------------------------------------
extern "C" void kernel_launch(void* const* d_in, const int* in_sizes, int n_in,
                              void* d_out, int out_size) {
    const float* x  = (const float*)d_in[0];
    const float* Wg = (const float*)d_in[1];
    const float* bg = (const float*)d_in[2];
    const float* W1 = (const float*)d_in[3];
    const float* b1 = (const float*)d_in[4];
    const float* W2 = (const float*)d_in[5];
    const float* b2 = (const float*)d_in[6];
    float* out = (float*)d_out;

    cudaFuncSetAttribute(gemm_mma<1>, cudaFuncAttributeMaxDynamicSharedMemorySize, SMEM_REQ);
    cudaFuncSetAttribute(gemm_mma<2>, cudaFuncAttributeMaxDynamicSharedMemorySize, SMEM_REQ);

    init_kernel<<<(MAX_SLOTS + 255) / 256, 256>>>();
    router_kernel<<<T_TOK / 8, 256>>>(x, Wg, bg);
    scan_kernel<<<1, 256>>>();
    scatter_kernel<<<T_TOK / 256, 256>>>();
    wsplit_kernel<<<65536, dim3(32, 8)>>>(W1, W2);
    xsplit_kernel<<<T_TOK * D_DIM / 4 / 256, 256>>>(x);
    gemm_mma<1><<<dim3(H_DIM / 128, MAX_TILES), 256, SMEM_REQ>>>(b1);
    gemm_mma<2><<<dim3(D_DIM / 128, MAX_TILES), 256, SMEM_REQ>>>(b2);
    combine_kernel<<<(T_TOK * (D_DIM / 4) + 255) / 256, 256>>>(out);
}